// round 1
// baseline (speedup 1.0000x reference)
#include <cuda_runtime.h>
#include <cuda_bf16.h>
#include <math.h>

#define N_ATOMS 10000
#define N_EDGES 250000
#define F_DIM   128
#define F3      384
#define N_RBF   20
#define CUTOFF  5.0f
#define EPSV    1e-8f

// ---------------- scratch (device globals; no allocation allowed) ----------------
__device__ float g_Wij[(size_t)N_EDGES * F3];     // 384 MB
__device__ float g_dir[(size_t)N_EDGES * 3];
__device__ float g_q   [N_ATOMS * F_DIM];
__device__ float g_mu  [N_ATOMS * 3 * F_DIM];
__device__ float g_h   [N_ATOMS * F_DIM];
__device__ float g_x   [N_ATOMS * F3];
__device__ float g_dq  [N_ATOMS * F_DIM];
__device__ float g_dmu [N_ATOMS * 3 * F_DIM];
__device__ float g_mumix[N_ATOMS * 3 * 2 * F_DIM];
__device__ float g_ctx [N_ATOMS * 2 * F_DIM];
__device__ float g_hm  [N_ATOMS * F_DIM];
__device__ float g_xm  [N_ATOMS * F3];

// ---------------- edge precompute: dir + Wij ----------------
__global__ void edge_pre(const float* __restrict__ R,
                         const int* __restrict__ idx_i,
                         const int* __restrict__ idx_j,
                         const float* __restrict__ offs,
                         const float* __restrict__ filt_W,
                         const float* __restrict__ filt_b) {
    long e = blockIdx.x;
    int t = threadIdx.x;  // 128 threads
    __shared__ float s_phi[N_RBF];
    __shared__ float s_d, s_fcut, s_dir[3];

    if (t == 0) {
        int i = idx_i[e], j = idx_j[e];
        float rx = R[j*3+0] - R[i*3+0] + offs[e*3+0];
        float ry = R[j*3+1] - R[i*3+1] + offs[e*3+1];
        float rz = R[j*3+2] - R[i*3+2] + offs[e*3+2];
        float d = sqrtf(rx*rx + ry*ry + rz*rz);
        s_d = d;
        float inv = 1.0f / d;
        s_dir[0] = rx*inv; s_dir[1] = ry*inv; s_dir[2] = rz*inv;
        s_fcut = (d < CUTOFF) ? 0.5f * (cosf(d * (float)(M_PI / 5.0)) + 1.0f) : 0.0f;
    }
    __syncthreads();
    if (t < N_RBF) {
        const float spacing = CUTOFF / (float)(N_RBF - 1);
        const float coeff = -0.5f / (spacing * spacing);
        float dd = s_d - (float)t * spacing;
        s_phi[t] = expf(coeff * dd * dd);
    }
    __syncthreads();

    float fc = s_fcut;
    #pragma unroll
    for (int p = 0; p < 3; ++p) {
        int c = t + p * F_DIM;
        float acc = filt_b[c];
        #pragma unroll
        for (int r = 0; r < N_RBF; ++r)
            acc += s_phi[r] * filt_W[r * F3 + c];
        g_Wij[e * F3 + c] = acc * fc;
    }
    if (t < 3) g_dir[e * 3 + t] = s_dir[t];
}

// ---------------- init: q = emb[Z], mu = 0 ----------------
__global__ void init_atoms(const int* __restrict__ Z, const float* __restrict__ emb) {
    int n = blockIdx.x, t = threadIdx.x;
    int z = Z[n];
    g_q[n * F_DIM + t] = emb[z * F_DIM + t];
    #pragma unroll
    for (int a = 0; a < 3; ++a) g_mu[(n * 3 + a) * F_DIM + t] = 0.0f;
}

// ---------------- simple tiled SGEMM: C = act(A[M,K] @ B[K,N] + bias) ----------------
// N multiple of 64, K multiple of 16. M guarded.
__global__ void sgemm(const float* __restrict__ A, const float* __restrict__ B,
                      const float* __restrict__ bias, float* __restrict__ C,
                      int M, int N, int K, int act) {
    const int BM = 64, BN = 64, BK = 16;
    __shared__ float As[BK][BM];
    __shared__ float Bs[BK][BN];
    int tid = threadIdx.x;               // 256 threads
    int row0 = blockIdx.y * BM;
    int col0 = blockIdx.x * BN;
    int tr = tid / 16, tc = tid % 16;    // 16x16 threads, 4x4 micro-tile
    float acc[4][4] = {};

    for (int k0 = 0; k0 < K; k0 += BK) {
        #pragma unroll
        for (int l = 0; l < 4; ++l) {
            int idx = tid + l * 256;
            int m = idx / BK, kk = idx % BK;
            int gr = row0 + m;
            As[kk][m] = (gr < M) ? A[(long)gr * K + k0 + kk] : 0.0f;
        }
        #pragma unroll
        for (int l = 0; l < 4; ++l) {
            int idx = tid + l * 256;
            int kk = idx / BN, n = idx % BN;
            Bs[kk][n] = B[(long)(k0 + kk) * N + col0 + n];
        }
        __syncthreads();
        #pragma unroll
        for (int kk = 0; kk < BK; ++kk) {
            float a[4], b[4];
            #pragma unroll
            for (int i = 0; i < 4; ++i) a[i] = As[kk][tr * 4 + i];
            #pragma unroll
            for (int j = 0; j < 4; ++j) b[j] = Bs[kk][tc * 4 + j];
            #pragma unroll
            for (int i = 0; i < 4; ++i)
                #pragma unroll
                for (int j = 0; j < 4; ++j)
                    acc[i][j] += a[i] * b[j];
        }
        __syncthreads();
    }
    #pragma unroll
    for (int i = 0; i < 4; ++i) {
        int r = row0 + tr * 4 + i;
        if (r >= M) continue;
        #pragma unroll
        for (int j = 0; j < 4; ++j) {
            int c = col0 + tc * 4 + j;
            float v = acc[i][j] + (bias ? bias[c] : 0.0f);
            if (act) v = v / (1.0f + expf(-v));   // silu
            C[(long)r * N + c] = v;
        }
    }
}

// ---------------- edge message pass with sorted-idx register accumulation ----------------
#define EPB 50
__global__ void edge_message(const int* __restrict__ idx_i, const int* __restrict__ idx_j) {
    int t = threadIdx.x;  // 128 threads = F_DIM
    long e0 = (long)blockIdx.x * EPB;
    long e1 = e0 + EPB; if (e1 > N_EDGES) e1 = N_EDGES;
    int cur = -1;
    float aq = 0.f, a0 = 0.f, a1 = 0.f, a2 = 0.f;

    for (long e = e0; e < e1; ++e) {
        int i = idx_i[e], j = idx_j[e];
        if (i != cur) {
            if (cur >= 0) {
                atomicAdd(&g_dq[cur * F_DIM + t], aq);
                atomicAdd(&g_dmu[(cur * 3 + 0) * F_DIM + t], a0);
                atomicAdd(&g_dmu[(cur * 3 + 1) * F_DIM + t], a1);
                atomicAdd(&g_dmu[(cur * 3 + 2) * F_DIM + t], a2);
            }
            cur = i; aq = a0 = a1 = a2 = 0.f;
        }
        const float* w = &g_Wij[e * F3];
        float w0 = __ldcs(&w[t]);
        float w1 = __ldcs(&w[F_DIM + t]);
        float w2 = __ldcs(&w[2 * F_DIM + t]);
        float xj0 = g_x[(long)j * F3 + t];
        float xj1 = g_x[(long)j * F3 + F_DIM + t];
        float xj2 = g_x[(long)j * F3 + 2 * F_DIM + t];
        float m0 = g_mu[(j * 3 + 0) * F_DIM + t];
        float m1 = g_mu[(j * 3 + 1) * F_DIM + t];
        float m2 = g_mu[(j * 3 + 2) * F_DIM + t];
        float d0 = g_dir[e * 3 + 0], d1 = g_dir[e * 3 + 1], d2 = g_dir[e * 3 + 2];

        aq += w0 * xj0;
        float dmuR  = w1 * xj1;
        float dmumu = w2 * xj2;
        a0 += dmuR * d0 + dmumu * m0;
        a1 += dmuR * d1 + dmumu * m1;
        a2 += dmuR * d2 + dmumu * m2;
    }
    if (cur >= 0) {
        atomicAdd(&g_dq[cur * F_DIM + t], aq);
        atomicAdd(&g_dmu[(cur * 3 + 0) * F_DIM + t], a0);
        atomicAdd(&g_dmu[(cur * 3 + 1) * F_DIM + t], a1);
        atomicAdd(&g_dmu[(cur * 3 + 2) * F_DIM + t], a2);
    }
}

// ---------------- apply message deltas ----------------
__global__ void apply_deltas() {
    int n = blockIdx.x, t = threadIdx.x;
    g_q[n * F_DIM + t] += g_dq[n * F_DIM + t];
    #pragma unroll
    for (int a = 0; a < 3; ++a)
        g_mu[(n * 3 + a) * F_DIM + t] += g_dmu[(n * 3 + a) * F_DIM + t];
}

// ---------------- mixing: ctx = [q, ||mu_V||] ----------------
__global__ void ctx_kernel() {
    int n = blockIdx.x, t = threadIdx.x;
    float s = EPSV;
    #pragma unroll
    for (int a = 0; a < 3; ++a) {
        float v = g_mumix[(n * 3 + a) * (2 * F_DIM) + t];
        s += v * v;
    }
    g_ctx[n * 2 * F_DIM + t] = g_q[n * F_DIM + t];
    g_ctx[n * 2 * F_DIM + F_DIM + t] = sqrtf(s);
}

// ---------------- mixing update ----------------
__global__ void mix_update() {
    int n = blockIdx.x, t = threadIdx.x;
    float dq   = g_xm[n * F3 + t];
    float dmu  = g_xm[n * F3 + F_DIM + t];
    float dqmu = g_xm[n * F3 + 2 * F_DIM + t];
    float s = 0.f;
    #pragma unroll
    for (int a = 0; a < 3; ++a) {
        float v = g_mumix[(n * 3 + a) * (2 * F_DIM) + t];
        float w = g_mumix[(n * 3 + a) * (2 * F_DIM) + F_DIM + t];
        s += v * w;
        g_mu[(n * 3 + a) * F_DIM + t] += dmu * w;
    }
    g_q[n * F_DIM + t] += dq + dqmu * s;
}

// ---------------- host launch ----------------
extern "C" void kernel_launch(void* const* d_in, const int* in_sizes, int n_in,
                              void* d_out, int out_size) {
    (void)in_sizes; (void)n_in;
    const int*   Z       = (const int*)  d_in[0];
    const float* R       = (const float*)d_in[1];
    const int*   idx_i   = (const int*)  d_in[2];
    const int*   idx_j   = (const int*)  d_in[3];
    const float* offs    = (const float*)d_in[4];
    const float* emb     = (const float*)d_in[5];
    const float* filt_W  = (const float*)d_in[6];
    const float* filt_b  = (const float*)d_in[7];
    const float* int_W1  = (const float*)d_in[8];
    const float* int_b1  = (const float*)d_in[9];
    const float* int_W2  = (const float*)d_in[10];
    const float* int_b2  = (const float*)d_in[11];
    const float* mix_Wmu = (const float*)d_in[12];
    const float* mix_W1  = (const float*)d_in[13];
    const float* mix_b1  = (const float*)d_in[14];
    const float* mix_W2  = (const float*)d_in[15];
    const float* mix_b2  = (const float*)d_in[16];
    float* out = (float*)d_out;
    (void)out_size;

    void *p_q, *p_mu, *p_h, *p_x, *p_dq, *p_dmu, *p_mumix, *p_ctx, *p_hm, *p_xm;
    cudaGetSymbolAddress(&p_q, g_q);
    cudaGetSymbolAddress(&p_mu, g_mu);
    cudaGetSymbolAddress(&p_h, g_h);
    cudaGetSymbolAddress(&p_x, g_x);
    cudaGetSymbolAddress(&p_dq, g_dq);
    cudaGetSymbolAddress(&p_dmu, g_dmu);
    cudaGetSymbolAddress(&p_mumix, g_mumix);
    cudaGetSymbolAddress(&p_ctx, g_ctx);
    cudaGetSymbolAddress(&p_hm, g_hm);
    cudaGetSymbolAddress(&p_xm, g_xm);

    // 1) edge precompute
    edge_pre<<<N_EDGES, 128>>>(R, idx_i, idx_j, offs, filt_W, filt_b);
    // 2) init
    init_atoms<<<N_ATOMS, 128>>>(Z, emb);

    dim3 blk(256);
    for (int it = 0; it < 3; ++it) {
        // interaction atom-wise MLP
        sgemm<<<dim3(F_DIM / 64, (N_ATOMS + 63) / 64), blk>>>(
            (const float*)p_q, int_W1 + (long)it * F_DIM * F_DIM,
            int_b1 + (long)it * F_DIM, (float*)p_h, N_ATOMS, F_DIM, F_DIM, 1);
        sgemm<<<dim3(F3 / 64, (N_ATOMS + 63) / 64), blk>>>(
            (const float*)p_h, int_W2 + (long)it * F_DIM * F3,
            int_b2 + (long)it * F3, (float*)p_x, N_ATOMS, F3, F_DIM, 0);

        // message pass
        cudaMemsetAsync(p_dq, 0, (size_t)N_ATOMS * F_DIM * sizeof(float));
        cudaMemsetAsync(p_dmu, 0, (size_t)N_ATOMS * 3 * F_DIM * sizeof(float));
        edge_message<<<(N_EDGES + EPB - 1) / EPB, 128>>>(idx_i, idx_j);
        apply_deltas<<<N_ATOMS, 128>>>();

        // mixing
        sgemm<<<dim3(2 * F_DIM / 64, (3 * N_ATOMS + 63) / 64), blk>>>(
            (const float*)p_mu, mix_Wmu + (long)it * F_DIM * 2 * F_DIM,
            nullptr, (float*)p_mumix, 3 * N_ATOMS, 2 * F_DIM, F_DIM, 0);
        ctx_kernel<<<N_ATOMS, 128>>>();
        sgemm<<<dim3(F_DIM / 64, (N_ATOMS + 63) / 64), blk>>>(
            (const float*)p_ctx, mix_W1 + (long)it * 2 * F_DIM * F_DIM,
            mix_b1 + (long)it * F_DIM, (float*)p_hm, N_ATOMS, F_DIM, 2 * F_DIM, 1);
        sgemm<<<dim3(F3 / 64, (N_ATOMS + 63) / 64), blk>>>(
            (const float*)p_hm, mix_W2 + (long)it * F_DIM * F3,
            mix_b2 + (long)it * F3, (float*)p_xm, N_ATOMS, F3, F_DIM, 0);
        mix_update<<<N_ATOMS, 128>>>();
    }

    // output: q [N,F] then mu [N,3,F]
    cudaMemcpyAsync(out, p_q, (size_t)N_ATOMS * F_DIM * sizeof(float),
                    cudaMemcpyDeviceToDevice);
    cudaMemcpyAsync(out + (size_t)N_ATOMS * F_DIM, p_mu,
                    (size_t)N_ATOMS * 3 * F_DIM * sizeof(float),
                    cudaMemcpyDeviceToDevice);
}